// round 7
// baseline (speedup 1.0000x reference)
#include <cuda_runtime.h>

#define N_NODES 100000
#define D       128
#define E_EDGES 600000

// ---- scratch (static device globals: allocation-free) ----
__device__ float g_B1[D * D];                 // B1[k][j] = W_w[j][k]          (for hp  = h @ B1 + Wb)
__device__ float g_B2[D * D];                 // B2[k][j] = sum_m Ww[m][k]H[m][j] (for hpH = h @ B2 + b2)
__device__ float g_b2[D];                     // b2[j]    = sum_m Wb[m] H[m][j]
__device__ float g_hp [(size_t)N_NODES * D];
__device__ float g_hpH[(size_t)N_NODES * D];

// ---------------------------------------------------------------------------
// Precompute combined weights. grid = D blocks (one per output column j),
// block = D threads (one per k). Trivial cost (~2M FMA total).
// ---------------------------------------------------------------------------
__global__ void prep_kernel(const float* __restrict__ Ww,
                            const float* __restrict__ Wb,
                            const float* __restrict__ H) {
    const int j = blockIdx.x;
    const int k = threadIdx.x;

    // transpose of W_w
    g_B1[k * D + j] = Ww[j * D + k];

    // B2[k][j] = sum_m Ww[m][k] * H[m][j]
    float acc = 0.f;
#pragma unroll 8
    for (int m = 0; m < D; ++m)
        acc = fmaf(Ww[m * D + k], H[m * D + j], acc);
    g_B2[k * D + j] = acc;

    if (k == 0) {
        float ab = 0.f;
#pragma unroll 8
        for (int m = 0; m < D; ++m)
            ab = fmaf(Wb[m], H[m * D + j], ab);
        g_b2[j] = ab;
    }
}

// ---------------------------------------------------------------------------
// Fused dual GEMM, vectorized-smem version.
//   hp [i][j] = sum_k h[i][k] * B1[k][j] + Wb[j]
//   hpH[i][j] = sum_k h[i][k] * B2[k][j] + b2[j]
// 512 threads (16 warps). Warp w owns rows w*8..w*8+7. Lane owns contiguous
// columns lane*4..lane*4+3 in BOTH outputs:
//   - av loads:  LDS.128 of h[row][k4..k4+3] (warp-broadcast, conflict-free)
//   - b  loads:  LDS.128 of W[k][lane*4..+3] (512B/warp, conflict-free)
//   - stores:    STG.128, coalesced
// smem: B1 (64KB) + B2 (64KB) + h tile (64KB) = 192KB -> 1 CTA/SM.
// ---------------------------------------------------------------------------
#define GEMM_THREADS 512
#define GEMM_ROWS    128

__global__ __launch_bounds__(GEMM_THREADS, 1)
void gemm_kernel(const float* __restrict__ hglob,
                 const float* __restrict__ Wb) {
    extern __shared__ float smem[];
    float* sW1 = smem;                  // D*D
    float* sW2 = smem + D * D;          // D*D
    float* sh  = smem + 2 * D * D;      // GEMM_ROWS*D

    const int tid  = threadIdx.x;
    const int warp = tid >> 5;
    const int lane = tid & 31;
    const int row0 = blockIdx.x * GEMM_ROWS;

    // --- load both weight matrices (float4, fully coalesced) ---
    {
        const float4* p1 = (const float4*)g_B1;
        const float4* p2 = (const float4*)g_B2;
        float4* s1 = (float4*)sW1;
        float4* s2 = (float4*)sW2;
#pragma unroll
        for (int t = 0; t < (D * D / 4) / GEMM_THREADS; ++t) {
            int i = tid + t * GEMM_THREADS;
            s1[i] = p1[i];
            s2[i] = p2[i];
        }
    }
    // --- load h tile (guard tail rows with zeros) ---
    {
        float4* st = (float4*)sh;
        const float4* pg = (const float4*)hglob;
#pragma unroll
        for (int t = 0; t < (GEMM_ROWS * D / 4) / GEMM_THREADS; ++t) {
            int i4   = tid + t * GEMM_THREADS;       // float4 index in tile
            int r    = i4 >> 5;                       // 32 float4 per row
            int c4   = i4 & 31;
            int grow = row0 + r;
            float4 v = make_float4(0.f, 0.f, 0.f, 0.f);
            if (grow < N_NODES) v = pg[(size_t)grow * 32 + c4];
            st[i4] = v;
        }
    }
    __syncthreads();

    // --- accumulators, init with biases (columns lane*4..lane*4+3) ---
    const int col0 = lane * 4;
    float4 bia1 = ((const float4*)Wb)[lane];
    float4 bia2 = ((const float4*)g_b2)[lane];

    float acc1[8][4], acc2[8][4];
#pragma unroll
    for (int r = 0; r < 8; ++r) {
        acc1[r][0] = bia1.x; acc1[r][1] = bia1.y; acc1[r][2] = bia1.z; acc1[r][3] = bia1.w;
        acc2[r][0] = bia2.x; acc2[r][1] = bia2.y; acc2[r][2] = bia2.z; acc2[r][3] = bia2.w;
    }

    const int rbase = warp * 8;

    // --- main loop: 4 k-steps per iteration, all smem traffic is LDS.128 ---
    for (int k4 = 0; k4 < D; k4 += 4) {
        float4 b1[4], b2[4];
#pragma unroll
        for (int kk = 0; kk < 4; ++kk) {
            b1[kk] = *(const float4*)&sW1[(k4 + kk) * D + col0];
            b2[kk] = *(const float4*)&sW2[(k4 + kk) * D + col0];
        }
#pragma unroll
        for (int r = 0; r < 8; ++r) {
            float4 av = *(const float4*)&sh[(rbase + r) * D + k4];  // broadcast
            float a[4] = {av.x, av.y, av.z, av.w};
#pragma unroll
            for (int kk = 0; kk < 4; ++kk) {
                acc1[r][0] = fmaf(a[kk], b1[kk].x, acc1[r][0]);
                acc1[r][1] = fmaf(a[kk], b1[kk].y, acc1[r][1]);
                acc1[r][2] = fmaf(a[kk], b1[kk].z, acc1[r][2]);
                acc1[r][3] = fmaf(a[kk], b1[kk].w, acc1[r][3]);
                acc2[r][0] = fmaf(a[kk], b2[kk].x, acc2[r][0]);
                acc2[r][1] = fmaf(a[kk], b2[kk].y, acc2[r][1]);
                acc2[r][2] = fmaf(a[kk], b2[kk].z, acc2[r][2]);
                acc2[r][3] = fmaf(a[kk], b2[kk].w, acc2[r][3]);
            }
        }
    }

    // --- store (STG.128, coalesced) ---
#pragma unroll
    for (int r = 0; r < 8; ++r) {
        int grow = row0 + rbase + r;
        if (grow < N_NODES) {
            float4* o1 = (float4*)&g_hp [(size_t)grow * D + col0];
            float4* o2 = (float4*)&g_hpH[(size_t)grow * D + col0];
            *o1 = make_float4(acc1[r][0], acc1[r][1], acc1[r][2], acc1[r][3]);
            *o2 = make_float4(acc2[r][0], acc2[r][1], acc2[r][2], acc2[r][3]);
        }
    }
}

// ---------------------------------------------------------------------------
// Edge kernel: one warp per edge. Lane i holds float4 i of the 128-float row.
// score[e] = || hp[src[e]] - hpH[dst[e]] ||^2
// NOTE: src/dst arrive as int32 (JAX x64 disabled -> "int64" arrays are int32).
// ---------------------------------------------------------------------------
__global__ void edge_kernel(const int* __restrict__ src,
                            const int* __restrict__ dst,
                            float* __restrict__ out) {
    const int wg   = (int)((blockIdx.x * (unsigned)blockDim.x + threadIdx.x) >> 5);
    const int lane = threadIdx.x & 31;
    if (wg >= E_EDGES) return;

    const int s = src[wg];
    const int d = dst[wg];

    const float4* ps = (const float4*)(g_hp  + (size_t)s * D);
    const float4* pd = (const float4*)(g_hpH + (size_t)d * D);
    float4 a = ps[lane];
    float4 b = pd[lane];

    float dx = a.x - b.x, dy = a.y - b.y, dz = a.z - b.z, dw = a.w - b.w;
    float acc = dx * dx + dy * dy + dz * dz + dw * dw;

#pragma unroll
    for (int o = 16; o > 0; o >>= 1)
        acc += __shfl_xor_sync(0xffffffffu, acc, o);

    if (lane == 0) out[wg] = acc;
}

// ---------------------------------------------------------------------------
extern "C" void kernel_launch(void* const* d_in, const int* in_sizes, int n_in,
                              void* d_out, int out_size) {
    const float* h   = (const float*)d_in[0];
    const int*   src = (const int*)d_in[1];
    const int*   dst = (const int*)d_in[2];
    const float* Ww  = (const float*)d_in[3];
    const float* Wb  = (const float*)d_in[4];
    const float* H   = (const float*)d_in[5];
    float*       out = (float*)d_out;

    (void)in_sizes; (void)n_in; (void)out_size;

    prep_kernel<<<D, D>>>(Ww, Wb, H);

    const int smem_bytes = (2 * D * D + GEMM_ROWS * D) * (int)sizeof(float);  // 192KB
    cudaFuncSetAttribute(gemm_kernel, cudaFuncAttributeMaxDynamicSharedMemorySize, smem_bytes);
    gemm_kernel<<<(N_NODES + GEMM_ROWS - 1) / GEMM_ROWS, GEMM_THREADS, smem_bytes>>>(h, Wb);

    const int ethreads = 256;                                  // 8 warps/block
    const int eblocks  = (E_EDGES + 7) / 8;                    // 1 warp per edge
    edge_kernel<<<eblocks, ethreads>>>(src, dst, out);
}

// round 10
// speedup vs baseline: 1.0740x; 1.0740x over previous
#include <cuda_runtime.h>

#define N_NODES 100000
#define D       128
#define E_EDGES 600000

// ---- scratch (static device globals: allocation-free) ----
__device__ float g_B1[D * D];                 // B1[k][j] = W_w[j][k]
__device__ float g_B2[D * D];                 // B2[k][j] = sum_m Ww[m][k]H[m][j]
__device__ float g_b2[D];                     // b2[j]    = sum_m Wb[m] H[m][j]
__device__ float g_hp [(size_t)N_NODES * D];
__device__ float g_hpH[(size_t)N_NODES * D];

// ---- packed fp32x2 helpers (SASS FFMA2; PTX-only encoding, exact IEEE fp32) ----
__device__ __forceinline__ void ffma2(unsigned long long& acc,
                                      unsigned long long a,
                                      unsigned long long b) {
    asm("fma.rn.f32x2 %0, %1, %2, %0;" : "+l"(acc) : "l"(a), "l"(b));
}
__device__ __forceinline__ unsigned long long pack2(float x) {
    unsigned long long r;
    asm("mov.b64 %0, {%1, %1};" : "=l"(r) : "f"(x));
    return r;
}
__device__ __forceinline__ unsigned long long pack2(float x, float y) {
    unsigned long long r;
    asm("mov.b64 %0, {%1, %2};" : "=l"(r) : "f"(x), "f"(y));
    return r;
}
__device__ __forceinline__ float2 unpack2(unsigned long long v) {
    float2 f;
    asm("mov.b64 {%0, %1}, %2;" : "=f"(f.x), "=f"(f.y) : "l"(v));
    return f;
}

// ---------------------------------------------------------------------------
// Precompute combined weights. grid = D (one block per output column j),
// block = D threads (one per k). v2: H column cached in smem so the m-loop is
// coalesced-LDG(Ww) + broadcast-LDS, unroll-8 for MLP.
// ---------------------------------------------------------------------------
__global__ void prep_kernel(const float* __restrict__ Ww,
                            const float* __restrict__ Wb,
                            const float* __restrict__ H) {
    __shared__ float sH[D];
    const int j = blockIdx.x;
    const int k = threadIdx.x;

    sH[k] = H[k * D + j];            // one strided load per thread, once
    // transpose of W_w (read coalesced over k)
    g_B1[k * D + j] = Ww[j * D + k];
    __syncthreads();

    float acc = 0.f;
#pragma unroll 8
    for (int m = 0; m < D; ++m)
        acc = fmaf(Ww[m * D + k], sH[m], acc);   // LDG coalesced + LDS broadcast
    g_B2[k * D + j] = acc;

    if (k == 0) {
        float ab = 0.f;
#pragma unroll 8
        for (int m = 0; m < D; ++m)
            ab = fmaf(Wb[m], sH[m], ab);
        g_b2[j] = ab;
    }
}

// ---------------------------------------------------------------------------
// Fused dual GEMM, packed-f32x2 version.
//   hp [i][j] = sum_k h[i][k] * B1[k][j] + Wb[j]
//   hpH[i][j] = sum_k h[i][k] * B2[k][j] + b2[j]
// 512 threads (16 warps). Warp w owns rows w*8..w*8+7. Lane owns contiguous
// columns lane*4..lane*4+3, held as two packed f32x2 accumulators per output.
//   - b loads:  LDS.128 reinterpreted as 2 packed u64 (no pack cost)
//   - a loads:  LDS.128 broadcast + mov.b64 duplication (alu pipe, overlaps fma)
//   - math:     FFMA2 -> half the fma-pipe issues of scalar FFMA
// smem: B1 (64KB) + B2 (64KB) + h tile (64KB) = 192KB -> 1 CTA/SM.
// ---------------------------------------------------------------------------
#define GEMM_THREADS 512
#define GEMM_ROWS    128

__global__ __launch_bounds__(GEMM_THREADS, 1)
void gemm_kernel(const float* __restrict__ hglob,
                 const float* __restrict__ Wb) {
    extern __shared__ float smem[];
    float* sW1 = smem;                  // D*D
    float* sW2 = smem + D * D;          // D*D
    float* sh  = smem + 2 * D * D;      // GEMM_ROWS*D

    const int tid  = threadIdx.x;
    const int warp = tid >> 5;
    const int lane = tid & 31;
    const int row0 = blockIdx.x * GEMM_ROWS;

    // --- load both weight matrices (float4, fully coalesced) ---
    {
        const float4* p1 = (const float4*)g_B1;
        const float4* p2 = (const float4*)g_B2;
        float4* s1 = (float4*)sW1;
        float4* s2 = (float4*)sW2;
#pragma unroll
        for (int t = 0; t < (D * D / 4) / GEMM_THREADS; ++t) {
            int i = tid + t * GEMM_THREADS;
            s1[i] = p1[i];
            s2[i] = p2[i];
        }
    }
    // --- load h tile (guard tail rows with zeros) ---
    {
        float4* st = (float4*)sh;
        const float4* pg = (const float4*)hglob;
#pragma unroll
        for (int t = 0; t < (GEMM_ROWS * D / 4) / GEMM_THREADS; ++t) {
            int i4   = tid + t * GEMM_THREADS;
            int r    = i4 >> 5;
            int c4   = i4 & 31;
            int grow = row0 + r;
            float4 v = make_float4(0.f, 0.f, 0.f, 0.f);
            if (grow < N_NODES) v = pg[(size_t)grow * 32 + c4];
            st[i4] = v;
        }
    }
    __syncthreads();

    // --- accumulators as packed pairs, init with biases ---
    const int col0 = lane * 4;
    float4 bia1 = ((const float4*)Wb)[lane];
    float4 bia2 = ((const float4*)g_b2)[lane];

    unsigned long long A1[8][2], A2[8][2];
    {
        unsigned long long b1lo = pack2(bia1.x, bia1.y), b1hi = pack2(bia1.z, bia1.w);
        unsigned long long b2lo = pack2(bia2.x, bia2.y), b2hi = pack2(bia2.z, bia2.w);
#pragma unroll
        for (int r = 0; r < 8; ++r) {
            A1[r][0] = b1lo; A1[r][1] = b1hi;
            A2[r][0] = b2lo; A2[r][1] = b2hi;
        }
    }

    const int rbase = warp * 8;

    // --- main loop: 4 k-steps per iteration ---
    for (int k4 = 0; k4 < D; k4 += 4) {
        ulonglong2 B1v[4], B2v[4];
#pragma unroll
        for (int kk = 0; kk < 4; ++kk) {
            B1v[kk] = *(const ulonglong2*)&sW1[(k4 + kk) * D + col0];
            B2v[kk] = *(const ulonglong2*)&sW2[(k4 + kk) * D + col0];
        }
#pragma unroll
        for (int r = 0; r < 8; ++r) {
            float4 av = *(const float4*)&sh[(rbase + r) * D + k4];  // broadcast
            unsigned long long ap[4] = {pack2(av.x), pack2(av.y), pack2(av.z), pack2(av.w)};
#pragma unroll
            for (int kk = 0; kk < 4; ++kk) {
                ffma2(A1[r][0], ap[kk], B1v[kk].x);
                ffma2(A1[r][1], ap[kk], B1v[kk].y);
                ffma2(A2[r][0], ap[kk], B2v[kk].x);
                ffma2(A2[r][1], ap[kk], B2v[kk].y);
            }
        }
    }

    // --- store (STG.128, coalesced) ---
#pragma unroll
    for (int r = 0; r < 8; ++r) {
        int grow = row0 + rbase + r;
        if (grow < N_NODES) {
            float2 lo1 = unpack2(A1[r][0]), hi1 = unpack2(A1[r][1]);
            float2 lo2 = unpack2(A2[r][0]), hi2 = unpack2(A2[r][1]);
            float4* o1 = (float4*)&g_hp [(size_t)grow * D + col0];
            float4* o2 = (float4*)&g_hpH[(size_t)grow * D + col0];
            *o1 = make_float4(lo1.x, lo1.y, hi1.x, hi1.y);
            *o2 = make_float4(lo2.x, lo2.y, hi2.x, hi2.y);
        }
    }
}

// ---------------------------------------------------------------------------
// Edge kernel: one warp per edge. Lane i holds float4 i of the 128-float row.
// score[e] = || hp[src[e]] - hpH[dst[e]] ||^2
// NOTE: src/dst arrive as int32 (JAX x64 disabled -> "int64" arrays are int32).
// ---------------------------------------------------------------------------
__global__ void edge_kernel(const int* __restrict__ src,
                            const int* __restrict__ dst,
                            float* __restrict__ out) {
    const int wg   = (int)((blockIdx.x * (unsigned)blockDim.x + threadIdx.x) >> 5);
    const int lane = threadIdx.x & 31;
    if (wg >= E_EDGES) return;

    const int s = src[wg];
    const int d = dst[wg];

    const float4* ps = (const float4*)(g_hp  + (size_t)s * D);
    const float4* pd = (const float4*)(g_hpH + (size_t)d * D);
    float4 a = ps[lane];
    float4 b = pd[lane];

    float dx = a.x - b.x, dy = a.y - b.y, dz = a.z - b.z, dw = a.w - b.w;
    float acc = dx * dx + dy * dy + dz * dz + dw * dw;

#pragma unroll
    for (int o = 16; o > 0; o >>= 1)
        acc += __shfl_xor_sync(0xffffffffu, acc, o);

    if (lane == 0) out[wg] = acc;
}

// ---------------------------------------------------------------------------
extern "C" void kernel_launch(void* const* d_in, const int* in_sizes, int n_in,
                              void* d_out, int out_size) {
    const float* h   = (const float*)d_in[0];
    const int*   src = (const int*)d_in[1];
    const int*   dst = (const int*)d_in[2];
    const float* Ww  = (const float*)d_in[3];
    const float* Wb  = (const float*)d_in[4];
    const float* H   = (const float*)d_in[5];
    float*       out = (float*)d_out;

    (void)in_sizes; (void)n_in; (void)out_size;

    prep_kernel<<<D, D>>>(Ww, Wb, H);

    const int smem_bytes = (2 * D * D + GEMM_ROWS * D) * (int)sizeof(float);  // 192KB
    cudaFuncSetAttribute(gemm_kernel, cudaFuncAttributeMaxDynamicSharedMemorySize, smem_bytes);
    gemm_kernel<<<(N_NODES + GEMM_ROWS - 1) / GEMM_ROWS, GEMM_THREADS, smem_bytes>>>(h, Wb);

    const int ethreads = 256;                                  // 8 warps/block
    const int eblocks  = (E_EDGES + 7) / 8;                    // 1 warp per edge
    edge_kernel<<<eblocks, ethreads>>>(src, dst, out);
}